// round 2
// baseline (speedup 1.0000x reference)
#include <cuda_runtime.h>
#include <cuda_bf16.h>
#include <cstdint>
#include <math.h>

#define BATCH 262144
#define GD 16
#define HID 256
#define RR 16
#define ZD 128
#define MTILE 64
#define NBLK (BATCH / MTILE)

// padded smem strides (floats) for conflict-free mma fragment LDS
#define XS_S 20
#define W1_S 264
#define H_S  260
#define W2_S 264
#define W3_S 24

// scratch between kernels (device globals: allocation-free)
__device__ float g_lamg[BATCH];
__device__ float g_d[BATCH * RR];

__device__ __forceinline__ uint32_t f2tf(float x) {
    uint32_t u;
    asm("cvt.rna.tf32.f32 %0, %1;" : "=r"(u) : "f"(x));
    return u;
}

__device__ __forceinline__ void mma8(float d[4], const uint32_t a[4],
                                     const uint32_t b[2], const float c[4]) {
    asm volatile(
        "mma.sync.aligned.m16n8k8.row.col.f32.tf32.tf32.f32 "
        "{%0,%1,%2,%3}, {%4,%5,%6,%7}, {%8,%9}, {%10,%11,%12,%13};\n"
        : "=f"(d[0]), "=f"(d[1]), "=f"(d[2]), "=f"(d[3])
        : "r"(a[0]), "r"(a[1]), "r"(a[2]), "r"(a[3]),
          "r"(b[0]), "r"(b[1]),
          "f"(c[0]), "f"(c[1]), "f"(c[2]), "f"(c[3]));
}

__device__ __forceinline__ void cpa16(float* s, const float* g) {
    uint32_t sa = (uint32_t)__cvta_generic_to_shared(s);
    asm volatile("cp.async.cg.shared.global [%0], [%1], 16;\n" ::"r"(sa), "l"(g));
}
__device__ __forceinline__ void cpcommit() { asm volatile("cp.async.commit_group;\n"); }
template <int N>
__device__ __forceinline__ void cpwait() { asm volatile("cp.async.wait_group %0;\n" ::"n"(N)); }

__device__ __forceinline__ float nan0(float v) { return isfinite(v) ? v : 0.f; }
__device__ __forceinline__ float silu_f(float x) { return x * (1.f / (1.f + __expf(-x))); }

// ============================================================================
// Kernel 1: fused MLP  pt -> (lam_g, d[r] = lam_para[r] - lam_g)
// ============================================================================
__global__ void __launch_bounds__(256, 1) mlp_kernel(
    const float* __restrict__ pt, const float* __restrict__ dt_norm_g,
    const float* __restrict__ U,
    const float* __restrict__ W1, const float* __restrict__ b1,
    const float* __restrict__ W2, const float* __restrict__ b2,
    const float* __restrict__ W3, const float* __restrict__ b3) {
    extern __shared__ float sm[];
    float* xs  = sm;           // 64*20   = 1280
    float* w1s = sm + 1280;    // 16*264  = 4224
    float* h1s = sm + 5504;    // 64*260  = 16640 (reused as hpart in GEMM3)
    float* h2s = sm + 22144;   // 64*260  = 16640
    float* w2s = sm + 38784;   // 2*32*264= 16896 (reused as w3s)
    // total 55680 floats = 222720 B dynamic

    __shared__ float b1s[256], b2s[256], b3s[16], cn2s[16];

    const int tid = threadIdx.x;
    const int wid = tid >> 5, lane = tid & 31;
    const int g = lane >> 2, q = lane & 3;
    const int r0 = blockIdx.x * MTILE;

    // --- prefetch W2 chunks 0,1 (overlaps GEMM1) ---
#pragma unroll
    for (int cc = 0; cc < 2; cc++) {
#pragma unroll
        for (int i = 0; i < 8; i++) {
            int idx = tid + i * 256;              // < 2048 float4s
            int kr = idx >> 6, c4 = (idx & 63) << 2;
            cpa16(&w2s[cc * 32 * W2_S + kr * W2_S + c4],
                  &W2[(size_t)(cc * 32 + kr) * 256 + c4]);
        }
        cpcommit();
    }

    // --- stage x tile (nan0) ---
#pragma unroll
    for (int i = 0; i < 4; i++) {
        int idx = tid + i * 256;                   // < 1024
        int rr = idx >> 4, cc = idx & 15;
        xs[rr * XS_S + cc] = nan0(pt[(size_t)(r0 + rr) * GD + cc]);
    }
    // --- stage W1 ---
#pragma unroll
    for (int i = 0; i < 16; i++) {
        int idx = tid + i * 256;                   // < 4096
        int kk = idx >> 8, cc = idx & 255;
        w1s[kk * W1_S + cc] = W1[kk * 256 + cc];
    }
    b1s[tid] = b1[tid];
    b2s[tid] = b2[tid];
    if (tid < 16) {
        b3s[tid] = b3[tid];
        float s = 0.f;
        for (int j = 0; j < ZD; j++) {
            float u = U[j * RR + tid];
            s += u * u;
        }
        cn2s[tid] = s;
    }
    __syncthreads();

    // ================= GEMM1: h1 = silu(x @ W1 + b1) =================
    {
        int wm = wid >> 2, wn = wid & 3;
        int rbase = wm * 32, cbase = wn * 64;
#pragma unroll
        for (int mt = 0; mt < 2; mt++) {
#pragma unroll
            for (int nt = 0; nt < 8; nt++) {
                float acc[4] = {0.f, 0.f, 0.f, 0.f};
#pragma unroll
                for (int ks = 0; ks < 2; ks++) {
                    int k0 = ks * 8;
                    int ra = rbase + mt * 16;
                    uint32_t a[4] = {
                        f2tf(xs[(ra + g) * XS_S + k0 + q]),
                        f2tf(xs[(ra + g + 8) * XS_S + k0 + q]),
                        f2tf(xs[(ra + g) * XS_S + k0 + q + 4]),
                        f2tf(xs[(ra + g + 8) * XS_S + k0 + q + 4])};
                    int cb = cbase + nt * 8;
                    uint32_t b[2] = {f2tf(w1s[(k0 + q) * W1_S + cb + g]),
                                     f2tf(w1s[(k0 + q + 4) * W1_S + cb + g])};
                    mma8(acc, a, b, acc);
                }
                int rr = rbase + mt * 16, cc = cbase + nt * 8;
                h1s[(rr + g) * H_S + cc + 2 * q]     = silu_f(acc[0] + b1s[cc + 2 * q]);
                h1s[(rr + g) * H_S + cc + 2 * q + 1] = silu_f(acc[1] + b1s[cc + 2 * q + 1]);
                h1s[(rr + g + 8) * H_S + cc + 2 * q]     = silu_f(acc[2] + b1s[cc + 2 * q]);
                h1s[(rr + g + 8) * H_S + cc + 2 * q + 1] = silu_f(acc[3] + b1s[cc + 2 * q + 1]);
            }
        }
    }
    __syncthreads();

    // ================= GEMM2: h2 = silu(h1 @ W2 + b2) =================
    {
        int wm = wid >> 2, wn = wid & 3;
        int rbase = wm * 32, cbase = wn * 64;
        float acc[2][8][4];
#pragma unroll
        for (int mt = 0; mt < 2; mt++)
#pragma unroll
            for (int nt = 0; nt < 8; nt++)
#pragma unroll
                for (int i = 0; i < 4; i++) acc[mt][nt][i] = 0.f;

        for (int c = 0; c < 8; c++) {
            if (c == 7) cpwait<0>(); else cpwait<1>();
            __syncthreads();
            const float* wb = w2s + (c & 1) * 32 * W2_S;
#pragma unroll
            for (int ks = 0; ks < 4; ks++) {
                int kg = c * 32 + ks * 8;   // global K for A (h1)
                int kl = ks * 8;            // local K within chunk
                uint32_t a[2][4];
#pragma unroll
                for (int mt = 0; mt < 2; mt++) {
                    int ra = rbase + mt * 16;
                    a[mt][0] = f2tf(h1s[(ra + g) * H_S + kg + q]);
                    a[mt][1] = f2tf(h1s[(ra + g + 8) * H_S + kg + q]);
                    a[mt][2] = f2tf(h1s[(ra + g) * H_S + kg + q + 4]);
                    a[mt][3] = f2tf(h1s[(ra + g + 8) * H_S + kg + q + 4]);
                }
#pragma unroll
                for (int nt = 0; nt < 8; nt++) {
                    int cb = cbase + nt * 8;
                    uint32_t b[2] = {f2tf(wb[(kl + q) * W2_S + cb + g]),
                                     f2tf(wb[(kl + q + 4) * W2_S + cb + g])};
                    mma8(acc[0][nt], a[0], b, acc[0][nt]);
                    mma8(acc[1][nt], a[1], b, acc[1][nt]);
                }
            }
            __syncthreads();
            if (c + 2 < 8) {
                int cc = c + 2;
#pragma unroll
                for (int i = 0; i < 8; i++) {
                    int idx = tid + i * 256;
                    int kr = idx >> 6, c4 = (idx & 63) << 2;
                    cpa16(&w2s[(cc & 1) * 32 * W2_S + kr * W2_S + c4],
                          &W2[(size_t)(cc * 32 + kr) * 256 + c4]);
                }
                cpcommit();
            }
        }
        // epilogue -> h2s
#pragma unroll
        for (int mt = 0; mt < 2; mt++) {
            int rr = rbase + mt * 16;
#pragma unroll
            for (int nt = 0; nt < 8; nt++) {
                int cc = cbase + nt * 8;
                h2s[(rr + g) * H_S + cc + 2 * q]     = silu_f(acc[mt][nt][0] + b2s[cc + 2 * q]);
                h2s[(rr + g) * H_S + cc + 2 * q + 1] = silu_f(acc[mt][nt][1] + b2s[cc + 2 * q + 1]);
                h2s[(rr + g + 8) * H_S + cc + 2 * q]     = silu_f(acc[mt][nt][2] + b2s[cc + 2 * q]);
                h2s[(rr + g + 8) * H_S + cc + 2 * q + 1] = silu_f(acc[mt][nt][3] + b2s[cc + 2 * q + 1]);
            }
        }
    }
    __syncthreads();

    // stage W3 into (now dead) w2s region
    float* w3s = w2s;
#pragma unroll
    for (int i = 0; i < 16; i++) {
        int idx = tid + i * 256;                   // < 4096 = 256*16
        int kk = idx >> 4, rr2 = idx & 15;
        w3s[kk * W3_S + rr2] = W3[kk * RR + rr2];
    }
    __syncthreads();

    // ================= GEMM3: h = h2 @ W3 (K split 4-ways over warps) ======
    float* hpart = h1s;  // [4][64][20], h1s dead
    {
        int wm = wid & 1, wk = wid >> 1;  // wk in 0..3: K slice of 64
        int rbase = wm * 32;
        float acc[2][2][4] = {};
#pragma unroll
        for (int ks = 0; ks < 8; ks++) {
            int k = wk * 64 + ks * 8;
            uint32_t a[2][4];
#pragma unroll
            for (int mt = 0; mt < 2; mt++) {
                int ra = rbase + mt * 16;
                a[mt][0] = f2tf(h2s[(ra + g) * H_S + k + q]);
                a[mt][1] = f2tf(h2s[(ra + g + 8) * H_S + k + q]);
                a[mt][2] = f2tf(h2s[(ra + g) * H_S + k + q + 4]);
                a[mt][3] = f2tf(h2s[(ra + g + 8) * H_S + k + q + 4]);
            }
#pragma unroll
            for (int nt = 0; nt < 2; nt++) {
                uint32_t b[2] = {f2tf(w3s[(k + q) * W3_S + nt * 8 + g]),
                                 f2tf(w3s[(k + q + 4) * W3_S + nt * 8 + g])};
                mma8(acc[0][nt], a[0], b, acc[0][nt]);
                mma8(acc[1][nt], a[1], b, acc[1][nt]);
            }
        }
#pragma unroll
        for (int mt = 0; mt < 2; mt++) {
            int rr = rbase + mt * 16;
#pragma unroll
            for (int nt = 0; nt < 2; nt++) {
                int cc = nt * 8;
                hpart[wk * 1280 + (rr + g) * 20 + cc + 2 * q]         = acc[mt][nt][0];
                hpart[wk * 1280 + (rr + g) * 20 + cc + 2 * q + 1]     = acc[mt][nt][1];
                hpart[wk * 1280 + (rr + g + 8) * 20 + cc + 2 * q]     = acc[mt][nt][2];
                hpart[wk * 1280 + (rr + g + 8) * 20 + cc + 2 * q + 1] = acc[mt][nt][3];
            }
        }
    }
    __syncthreads();

    // ================= per-row epilogue =================
    if (tid < 64) {
        int row = tid;
        float s[16];
        float fro2 = 0.f;
#pragma unroll
        for (int r = 0; r < 16; r++) {
            float v = hpart[0 * 1280 + row * 20 + r] + hpart[1 * 1280 + row * 20 + r] +
                      hpart[2 * 1280 + row * 20 + r] + hpart[3 * 1280 + row * 20 + r] +
                      b3s[r];
            float sr = 2.f / (1.f + __expf(-v));
            s[r] = sr;
            fro2 += sr * sr * cn2s[r];
        }
        float fro = sqrtf(fro2);
        // cap = 0.5 * 0.1 * sqrt(128*16)
        float scale = fminf(2.2627416997969522f / fmaxf(fro, 1e-9f), 1.f);

        float v = dt_norm_g[r0 + row];
        if (isnan(v)) v = 0.f;
        v = fminf(fmaxf(v, 0.f), 1.f);
        float logdt = fminf(-3.f + v * 11.f, 2.7781512503836436f);  // log10(600)
        float dt = fmaxf(expf(logdt * 2.302585092994046f), 1e-30f);
        float lamg = expf(-0.1f * dt);
        g_lamg[r0 + row] = lamg;
#pragma unroll
        for (int r = 0; r < 16; r++) {
            float ss = s[r] * scale;
            float lp = expf(-ss * ss * dt) * lamg;
            g_d[(size_t)(r0 + row) * 16 + r] = lp - lamg;
        }
    }
}

// ============================================================================
// Kernel 2: z_next = lam_g*z + ((lam_para - lam_g) .* (z@U)) @ U^T
// ============================================================================
__global__ void __launch_bounds__(256, 3) dyn_kernel(
    const float* __restrict__ z, const float* __restrict__ U,
    float* __restrict__ out) {
    extern __shared__ float sm2[];
    float* zs = sm2;            // 64*132 = 8448
    float* Us = sm2 + 8448;     // 128*24 = 3072 (U[j][r] at j*24+r)
    float* Ut = sm2 + 11520;    // 16*136 = 2176 (U^T[r][j] at r*136+j)
    float* cs = sm2 + 13696;    // 64*20  = 1280
    float* lg = sm2 + 14976;    // 64
    // total 15040 floats = 60160 B

    const int tid = threadIdx.x;
    const int wid = tid >> 5, lane = tid & 31;
    const int g = lane >> 2, q = lane & 3;
    const int r0 = blockIdx.x * MTILE;

    // --- stage z (nan0, float4) ---
#pragma unroll
    for (int i = 0; i < 8; i++) {
        int idx = tid + i * 256;                    // < 2048 float4s
        int row = idx >> 5, c4 = (idx & 31) << 2;
        float4 v = *reinterpret_cast<const float4*>(&z[(size_t)(r0 + row) * ZD + c4]);
        v.x = nan0(v.x); v.y = nan0(v.y); v.z = nan0(v.z); v.w = nan0(v.w);
        *reinterpret_cast<float4*>(&zs[row * 132 + c4]) = v;
    }
    // --- stage U both layouts ---
#pragma unroll
    for (int i = 0; i < 8; i++) {
        int idx = tid + i * 256;                    // < 2048
        int j = idx >> 4, r = idx & 15;
        float v = nan0(U[j * RR + r]);
        Us[j * 24 + r] = v;
        Ut[r * 136 + j] = v;
    }
    if (tid < 64) lg[tid] = g_lamg[r0 + tid];
    __syncthreads();

    // ===== GEMM A: cs[row][r] = d[row][r] * (z @ U)[row][r] =====
    {
        int mt = wid >> 1, nt = wid & 1;
        int rbase = mt * 16, cbase = nt * 8;
        float acc[4] = {0.f, 0.f, 0.f, 0.f};
#pragma unroll
        for (int k = 0; k < 16; k++) {
            int k0 = k * 8;
            uint32_t a[4] = {
                f2tf(zs[(rbase + g) * 132 + k0 + q]),
                f2tf(zs[(rbase + g + 8) * 132 + k0 + q]),
                f2tf(zs[(rbase + g) * 132 + k0 + q + 4]),
                f2tf(zs[(rbase + g + 8) * 132 + k0 + q + 4])};
            uint32_t b[2] = {f2tf(Us[(k0 + q) * 24 + cbase + g]),
                             f2tf(Us[(k0 + q + 4) * 24 + cbase + g])};
            mma8(acc, a, b, acc);
        }
        int row0 = rbase + g, row1 = rbase + g + 8;
        int c0 = cbase + 2 * q, c1 = c0 + 1;
        cs[row0 * 20 + c0] = acc[0] * g_d[(size_t)(r0 + row0) * 16 + c0];
        cs[row0 * 20 + c1] = acc[1] * g_d[(size_t)(r0 + row0) * 16 + c1];
        cs[row1 * 20 + c0] = acc[2] * g_d[(size_t)(r0 + row1) * 16 + c0];
        cs[row1 * 20 + c1] = acc[3] * g_d[(size_t)(r0 + row1) * 16 + c1];
    }
    __syncthreads();

    // ===== GEMM B + identity: zs[row][j] = lg[row]*zs[row][j] + (cs @ Ut)[row][j]
    {
        int wm = wid >> 1, wn = wid & 1;
        int rbase = wm * 16;
        float acc[8][4];
#pragma unroll
        for (int nt = 0; nt < 8; nt++)
#pragma unroll
            for (int i = 0; i < 4; i++) acc[nt][i] = 0.f;
#pragma unroll
        for (int ks = 0; ks < 2; ks++) {
            int k0 = ks * 8;
            uint32_t a[4] = {
                f2tf(cs[(rbase + g) * 20 + k0 + q]),
                f2tf(cs[(rbase + g + 8) * 20 + k0 + q]),
                f2tf(cs[(rbase + g) * 20 + k0 + q + 4]),
                f2tf(cs[(rbase + g + 8) * 20 + k0 + q + 4])};
#pragma unroll
            for (int nt = 0; nt < 8; nt++) {
                int cb = (wn * 8 + nt) * 8;
                uint32_t b[2] = {f2tf(Ut[(k0 + q) * 136 + cb + g]),
                                 f2tf(Ut[(k0 + q + 4) * 136 + cb + g])};
                mma8(acc[nt], a, b, acc[nt]);
            }
        }
        int row0 = rbase + g, row1 = rbase + g + 8;
        float l0 = lg[row0], l1 = lg[row1];
#pragma unroll
        for (int nt = 0; nt < 8; nt++) {
            int cb = (wn * 8 + nt) * 8;
            int c0 = cb + 2 * q, c1 = c0 + 1;
            zs[row0 * 132 + c0] = l0 * zs[row0 * 132 + c0] + acc[nt][0];
            zs[row0 * 132 + c1] = l0 * zs[row0 * 132 + c1] + acc[nt][1];
            zs[row1 * 132 + c0] = l1 * zs[row1 * 132 + c0] + acc[nt][2];
            zs[row1 * 132 + c1] = l1 * zs[row1 * 132 + c1] + acc[nt][3];
        }
    }
    __syncthreads();

    // --- coalesced float4 store ---
#pragma unroll
    for (int i = 0; i < 8; i++) {
        int idx = tid + i * 256;
        int row = idx >> 5, c4 = (idx & 31) << 2;
        float4 v = *reinterpret_cast<const float4*>(&zs[row * 132 + c4]);
        *reinterpret_cast<float4*>(&out[(size_t)(r0 + row) * ZD + c4]) = v;
    }
}

extern "C" void kernel_launch(void* const* d_in, const int* in_sizes, int n_in,
                              void* d_out, int out_size) {
    const float* pt      = (const float*)d_in[0];
    const float* z       = (const float*)d_in[1];
    const float* dt_norm = (const float*)d_in[2];
    const float* base_U  = (const float*)d_in[3];
    const float* W1      = (const float*)d_in[4];
    const float* b1      = (const float*)d_in[5];
    const float* W2      = (const float*)d_in[6];
    const float* b2      = (const float*)d_in[7];
    const float* W3      = (const float*)d_in[8];
    const float* b3      = (const float*)d_in[9];
    float* out = (float*)d_out;

    cudaFuncSetAttribute(mlp_kernel, cudaFuncAttributeMaxDynamicSharedMemorySize, 222720);
    cudaFuncSetAttribute(dyn_kernel, cudaFuncAttributeMaxDynamicSharedMemorySize, 60160);

    mlp_kernel<<<NBLK, 256, 222720>>>(pt, dt_norm, base_U, W1, b1, W2, b2, W3, b3);
    dyn_kernel<<<NBLK, 256, 60160>>>(z, base_U, out);
}

// round 3
// speedup vs baseline: 1.2075x; 1.2075x over previous
#include <cuda_runtime.h>
#include <cuda_bf16.h>
#include <cstdint>
#include <math.h>

#define BATCH 262144
#define GD 16
#define HID 256
#define RR 16
#define ZD 128
#define MTILE 64
#define NBLK (BATCH / MTILE)

// padded smem strides (floats) for conflict-free mma fragment LDS
#define XS_S 20
#define W1_S 264
#define H_S  260
#define W2_S 264
#define W3_S 24

// scratch between kernels (device globals: allocation-free)
__device__ float g_lamg[BATCH];
__device__ float g_d[BATCH * RR];

// raw fp32 bits into mma.tf32 (HW truncates low mantissa bits; no cvt needed)
__device__ __forceinline__ uint32_t fbits(float x) { return __float_as_uint(x); }

__device__ __forceinline__ void mma8(float d[4], const uint32_t a[4],
                                     const uint32_t b[2], const float c[4]) {
    asm volatile(
        "mma.sync.aligned.m16n8k8.row.col.f32.tf32.tf32.f32 "
        "{%0,%1,%2,%3}, {%4,%5,%6,%7}, {%8,%9}, {%10,%11,%12,%13};\n"
        : "=f"(d[0]), "=f"(d[1]), "=f"(d[2]), "=f"(d[3])
        : "r"(a[0]), "r"(a[1]), "r"(a[2]), "r"(a[3]),
          "r"(b[0]), "r"(b[1]),
          "f"(c[0]), "f"(c[1]), "f"(c[2]), "f"(c[3]));
}

__device__ __forceinline__ void cpa16(float* s, const float* g) {
    uint32_t sa = (uint32_t)__cvta_generic_to_shared(s);
    asm volatile("cp.async.cg.shared.global [%0], [%1], 16;\n" ::"r"(sa), "l"(g));
}
__device__ __forceinline__ void cpcommit() { asm volatile("cp.async.commit_group;\n"); }
template <int N>
__device__ __forceinline__ void cpwait() { asm volatile("cp.async.wait_group %0;\n" ::"n"(N)); }

__device__ __forceinline__ float nan0(float v) { return isfinite(v) ? v : 0.f; }
__device__ __forceinline__ float silu_f(float x) { return x * (1.f / (1.f + __expf(-x))); }

// ============================================================================
// Kernel 1: fused MLP  pt -> (lam_g, d[r] = lam_para[r] - lam_g)
// 512 threads (16 warps) per 64-row tile.
// ============================================================================
__global__ void __launch_bounds__(512, 1) mlp_kernel(
    const float* __restrict__ pt, const float* __restrict__ dt_norm_g,
    const float* __restrict__ U,
    const float* __restrict__ W1, const float* __restrict__ b1,
    const float* __restrict__ W2, const float* __restrict__ b2,
    const float* __restrict__ W3, const float* __restrict__ b3) {
    extern __shared__ float sm[];
    float* xs  = sm;           // 64*20   = 1280
    float* w1s = sm + 1280;    // 16*264  = 4224
    float* h1s = sm + 5504;    // 64*260  = 16640 (reused as hpart in GEMM3)
    float* h2s = sm + 22144;   // 64*260  = 16640
    float* w2s = sm + 38784;   // 2*32*264= 16896 (reused as w3s)
    // total 55680 floats = 222720 B dynamic

    __shared__ float b1s[256], b2s[256], b3s[16], cn2s[16];

    const int tid = threadIdx.x;
    const int wid = tid >> 5, lane = tid & 31;
    const int g = lane >> 2, q = lane & 3;
    const int r0 = blockIdx.x * MTILE;

    // --- prefetch W2 chunks 0,1 (overlaps GEMM1) ---
#pragma unroll
    for (int cc = 0; cc < 2; cc++) {
#pragma unroll
        for (int i = 0; i < 4; i++) {
            int idx = tid + i * 512;              // < 2048 float4s
            int kr = idx >> 6, c4 = (idx & 63) << 2;
            cpa16(&w2s[cc * 32 * W2_S + kr * W2_S + c4],
                  &W2[(size_t)(cc * 32 + kr) * 256 + c4]);
        }
        cpcommit();
    }

    // --- stage x tile (nan0) ---
#pragma unroll
    for (int i = 0; i < 2; i++) {
        int idx = tid + i * 512;                   // < 1024
        int rr = idx >> 4, cc = idx & 15;
        xs[rr * XS_S + cc] = nan0(pt[(size_t)(r0 + rr) * GD + cc]);
    }
    // --- stage W1 ---
#pragma unroll
    for (int i = 0; i < 8; i++) {
        int idx = tid + i * 512;                   // < 4096
        int kk = idx >> 8, cc = idx & 255;
        w1s[kk * W1_S + cc] = W1[kk * 256 + cc];
    }
    if (tid < 256) {
        b1s[tid] = b1[tid];
        b2s[tid] = b2[tid];
    }
    if (tid < 16) {
        b3s[tid] = b3[tid];
        float s = 0.f;
        for (int j = 0; j < ZD; j++) {
            float u = U[j * RR + tid];
            s += u * u;
        }
        cn2s[tid] = s;
    }
    __syncthreads();

    // warp tiling for GEMM1/GEMM2: 2 x 8 warps, each 32 rows x 32 cols
    const int wm = wid >> 3, wn = wid & 7;
    const int rbase = wm * 32, cbase = wn * 32;

    // ================= GEMM1: h1 = silu(x @ W1 + b1) =================
    {
#pragma unroll
        for (int mt = 0; mt < 2; mt++) {
#pragma unroll
            for (int nt = 0; nt < 4; nt++) {
                float acc[4] = {0.f, 0.f, 0.f, 0.f};
#pragma unroll
                for (int ks = 0; ks < 2; ks++) {
                    int k0 = ks * 8;
                    int ra = rbase + mt * 16;
                    uint32_t a[4] = {
                        fbits(xs[(ra + g) * XS_S + k0 + q]),
                        fbits(xs[(ra + g + 8) * XS_S + k0 + q]),
                        fbits(xs[(ra + g) * XS_S + k0 + q + 4]),
                        fbits(xs[(ra + g + 8) * XS_S + k0 + q + 4])};
                    int cb = cbase + nt * 8;
                    uint32_t b[2] = {fbits(w1s[(k0 + q) * W1_S + cb + g]),
                                     fbits(w1s[(k0 + q + 4) * W1_S + cb + g])};
                    mma8(acc, a, b, acc);
                }
                int rr = rbase + mt * 16, cc = cbase + nt * 8;
                h1s[(rr + g) * H_S + cc + 2 * q]     = silu_f(acc[0] + b1s[cc + 2 * q]);
                h1s[(rr + g) * H_S + cc + 2 * q + 1] = silu_f(acc[1] + b1s[cc + 2 * q + 1]);
                h1s[(rr + g + 8) * H_S + cc + 2 * q]     = silu_f(acc[2] + b1s[cc + 2 * q]);
                h1s[(rr + g + 8) * H_S + cc + 2 * q + 1] = silu_f(acc[3] + b1s[cc + 2 * q + 1]);
            }
        }
    }
    __syncthreads();

    // ================= GEMM2: h2 = silu(h1 @ W2 + b2) =================
    {
        float acc[2][4][4];
#pragma unroll
        for (int mt = 0; mt < 2; mt++)
#pragma unroll
            for (int nt = 0; nt < 4; nt++)
#pragma unroll
                for (int i = 0; i < 4; i++) acc[mt][nt][i] = 0.f;

        for (int c = 0; c < 8; c++) {
            if (c == 7) cpwait<0>(); else cpwait<1>();
            __syncthreads();
            const float* wb = w2s + (c & 1) * 32 * W2_S;
#pragma unroll
            for (int ks = 0; ks < 4; ks++) {
                int kg = c * 32 + ks * 8;   // global K for A (h1)
                int kl = ks * 8;            // local K within chunk
                uint32_t a[2][4];
#pragma unroll
                for (int mt = 0; mt < 2; mt++) {
                    int ra = rbase + mt * 16;
                    a[mt][0] = fbits(h1s[(ra + g) * H_S + kg + q]);
                    a[mt][1] = fbits(h1s[(ra + g + 8) * H_S + kg + q]);
                    a[mt][2] = fbits(h1s[(ra + g) * H_S + kg + q + 4]);
                    a[mt][3] = fbits(h1s[(ra + g + 8) * H_S + kg + q + 4]);
                }
#pragma unroll
                for (int nt = 0; nt < 4; nt++) {
                    int cb = cbase + nt * 8;
                    uint32_t b[2] = {fbits(wb[(kl + q) * W2_S + cb + g]),
                                     fbits(wb[(kl + q + 4) * W2_S + cb + g])};
                    mma8(acc[0][nt], a[0], b, acc[0][nt]);
                    mma8(acc[1][nt], a[1], b, acc[1][nt]);
                }
            }
            __syncthreads();
            if (c + 2 < 8) {
                int cc = c + 2;
#pragma unroll
                for (int i = 0; i < 4; i++) {
                    int idx = tid + i * 512;
                    int kr = idx >> 6, c4 = (idx & 63) << 2;
                    cpa16(&w2s[(cc & 1) * 32 * W2_S + kr * W2_S + c4],
                          &W2[(size_t)(cc * 32 + kr) * 256 + c4]);
                }
                cpcommit();
            }
        }
        // epilogue -> h2s
#pragma unroll
        for (int mt = 0; mt < 2; mt++) {
            int rr = rbase + mt * 16;
#pragma unroll
            for (int nt = 0; nt < 4; nt++) {
                int cc = cbase + nt * 8;
                h2s[(rr + g) * H_S + cc + 2 * q]     = silu_f(acc[mt][nt][0] + b2s[cc + 2 * q]);
                h2s[(rr + g) * H_S + cc + 2 * q + 1] = silu_f(acc[mt][nt][1] + b2s[cc + 2 * q + 1]);
                h2s[(rr + g + 8) * H_S + cc + 2 * q]     = silu_f(acc[mt][nt][2] + b2s[cc + 2 * q]);
                h2s[(rr + g + 8) * H_S + cc + 2 * q + 1] = silu_f(acc[mt][nt][3] + b2s[cc + 2 * q + 1]);
            }
        }
    }
    __syncthreads();

    // stage W3 into (now dead) w2s region
    float* w3s = w2s;
#pragma unroll
    for (int i = 0; i < 8; i++) {
        int idx = tid + i * 512;                   // < 4096 = 256*16
        int kk = idx >> 4, rr2 = idx & 15;
        w3s[kk * W3_S + rr2] = W3[kk * RR + rr2];
    }
    __syncthreads();

    // ================= GEMM3: h = h2 @ W3 (K split 8-ways over warps) ======
    float* hpart = h1s;  // [8][64][20], h1s dead
    {
        int wm3 = wid & 1, wk = wid >> 1;  // wk in 0..7: K slice of 32
        int rb3 = wm3 * 32;
        float acc[2][2][4] = {};
#pragma unroll
        for (int ks = 0; ks < 4; ks++) {
            int k = wk * 32 + ks * 8;
            uint32_t a[2][4];
#pragma unroll
            for (int mt = 0; mt < 2; mt++) {
                int ra = rb3 + mt * 16;
                a[mt][0] = fbits(h2s[(ra + g) * H_S + k + q]);
                a[mt][1] = fbits(h2s[(ra + g + 8) * H_S + k + q]);
                a[mt][2] = fbits(h2s[(ra + g) * H_S + k + q + 4]);
                a[mt][3] = fbits(h2s[(ra + g + 8) * H_S + k + q + 4]);
            }
#pragma unroll
            for (int nt = 0; nt < 2; nt++) {
                uint32_t b[2] = {fbits(w3s[(k + q) * W3_S + nt * 8 + g]),
                                 fbits(w3s[(k + q + 4) * W3_S + nt * 8 + g])};
                mma8(acc[0][nt], a[0], b, acc[0][nt]);
                mma8(acc[1][nt], a[1], b, acc[1][nt]);
            }
        }
#pragma unroll
        for (int mt = 0; mt < 2; mt++) {
            int rr = rb3 + mt * 16;
#pragma unroll
            for (int nt = 0; nt < 2; nt++) {
                int cc = nt * 8;
                hpart[wk * 1280 + (rr + g) * 20 + cc + 2 * q]         = acc[mt][nt][0];
                hpart[wk * 1280 + (rr + g) * 20 + cc + 2 * q + 1]     = acc[mt][nt][1];
                hpart[wk * 1280 + (rr + g + 8) * 20 + cc + 2 * q]     = acc[mt][nt][2];
                hpart[wk * 1280 + (rr + g + 8) * 20 + cc + 2 * q + 1] = acc[mt][nt][3];
            }
        }
    }
    __syncthreads();

    // ================= per-row epilogue =================
    if (tid < 64) {
        int row = tid;
        float s[16];
        float fro2 = 0.f;
#pragma unroll
        for (int r = 0; r < 16; r++) {
            float v = b3s[r];
#pragma unroll
            for (int p = 0; p < 8; p++) v += hpart[p * 1280 + row * 20 + r];
            float sr = 2.f / (1.f + __expf(-v));
            s[r] = sr;
            fro2 += sr * sr * cn2s[r];
        }
        float fro = sqrtf(fro2);
        // cap = 0.5 * 0.1 * sqrt(128*16)
        float scale = fminf(2.2627416997969522f / fmaxf(fro, 1e-9f), 1.f);

        float v = dt_norm_g[r0 + row];
        if (isnan(v)) v = 0.f;
        v = fminf(fmaxf(v, 0.f), 1.f);
        float logdt = fminf(-3.f + v * 11.f, 2.7781512503836436f);  // log10(600)
        float dt = fmaxf(expf(logdt * 2.302585092994046f), 1e-30f);
        float lamg = expf(-0.1f * dt);
        g_lamg[r0 + row] = lamg;
#pragma unroll
        for (int r = 0; r < 16; r++) {
            float ss = s[r] * scale;
            float lp = expf(-ss * ss * dt) * lamg;
            g_d[(size_t)(r0 + row) * 16 + r] = lp - lamg;
        }
    }
}

// ============================================================================
// Kernel 2: z_next = lam_g*z + ((lam_para - lam_g) .* (z@U)) @ U^T
// ============================================================================
__global__ void __launch_bounds__(256, 3) dyn_kernel(
    const float* __restrict__ z, const float* __restrict__ U,
    float* __restrict__ out) {
    extern __shared__ float sm2[];
    float* zs = sm2;            // 64*132 = 8448
    float* Us = sm2 + 8448;     // 128*24 = 3072 (U[j][r] at j*24+r)
    float* Ut = sm2 + 11520;    // 16*136 = 2176 (U^T[r][j] at r*136+j)
    float* cs = sm2 + 13696;    // 64*20  = 1280
    float* lg = sm2 + 14976;    // 64
    // total 15040 floats = 60160 B

    const int tid = threadIdx.x;
    const int wid = tid >> 5, lane = tid & 31;
    const int g = lane >> 2, q = lane & 3;
    const int r0 = blockIdx.x * MTILE;

    // --- stage z (nan0, float4) ---
#pragma unroll
    for (int i = 0; i < 8; i++) {
        int idx = tid + i * 256;                    // < 2048 float4s
        int row = idx >> 5, c4 = (idx & 31) << 2;
        float4 v = *reinterpret_cast<const float4*>(&z[(size_t)(r0 + row) * ZD + c4]);
        v.x = nan0(v.x); v.y = nan0(v.y); v.z = nan0(v.z); v.w = nan0(v.w);
        *reinterpret_cast<float4*>(&zs[row * 132 + c4]) = v;
    }
    // --- stage U both layouts ---
#pragma unroll
    for (int i = 0; i < 8; i++) {
        int idx = tid + i * 256;                    // < 2048
        int j = idx >> 4, r = idx & 15;
        float v = nan0(U[j * RR + r]);
        Us[j * 24 + r] = v;
        Ut[r * 136 + j] = v;
    }
    if (tid < 64) lg[tid] = g_lamg[r0 + tid];
    __syncthreads();

    // ===== GEMM A: cs[row][r] = d[row][r] * (z @ U)[row][r] =====
    {
        int mt = wid >> 1, nt = wid & 1;
        int rbase = mt * 16, cbase = nt * 8;
        float acc[4] = {0.f, 0.f, 0.f, 0.f};
#pragma unroll
        for (int k = 0; k < 16; k++) {
            int k0 = k * 8;
            uint32_t a[4] = {
                fbits(zs[(rbase + g) * 132 + k0 + q]),
                fbits(zs[(rbase + g + 8) * 132 + k0 + q]),
                fbits(zs[(rbase + g) * 132 + k0 + q + 4]),
                fbits(zs[(rbase + g + 8) * 132 + k0 + q + 4])};
            uint32_t b[2] = {fbits(Us[(k0 + q) * 24 + cbase + g]),
                             fbits(Us[(k0 + q + 4) * 24 + cbase + g])};
            mma8(acc, a, b, acc);
        }
        int row0 = rbase + g, row1 = rbase + g + 8;
        int c0 = cbase + 2 * q, c1 = c0 + 1;
        cs[row0 * 20 + c0] = acc[0] * g_d[(size_t)(r0 + row0) * 16 + c0];
        cs[row0 * 20 + c1] = acc[1] * g_d[(size_t)(r0 + row0) * 16 + c1];
        cs[row1 * 20 + c0] = acc[2] * g_d[(size_t)(r0 + row1) * 16 + c0];
        cs[row1 * 20 + c1] = acc[3] * g_d[(size_t)(r0 + row1) * 16 + c1];
    }
    __syncthreads();

    // ===== GEMM B + identity: zs[row][j] = lg[row]*zs[row][j] + (cs @ Ut)[row][j]
    {
        int wm = wid >> 1, wn = wid & 1;
        int rbase = wm * 16;
        float acc[8][4];
#pragma unroll
        for (int nt = 0; nt < 8; nt++)
#pragma unroll
            for (int i = 0; i < 4; i++) acc[nt][i] = 0.f;
#pragma unroll
        for (int ks = 0; ks < 2; ks++) {
            int k0 = ks * 8;
            uint32_t a[4] = {
                fbits(cs[(rbase + g) * 20 + k0 + q]),
                fbits(cs[(rbase + g + 8) * 20 + k0 + q]),
                fbits(cs[(rbase + g) * 20 + k0 + q + 4]),
                fbits(cs[(rbase + g + 8) * 20 + k0 + q + 4])};
#pragma unroll
            for (int nt = 0; nt < 8; nt++) {
                int cb = (wn * 8 + nt) * 8;
                uint32_t b[2] = {fbits(Ut[(k0 + q) * 136 + cb + g]),
                                 fbits(Ut[(k0 + q + 4) * 136 + cb + g])};
                mma8(acc[nt], a, b, acc[nt]);
            }
        }
        int row0 = rbase + g, row1 = rbase + g + 8;
        float l0 = lg[row0], l1 = lg[row1];
#pragma unroll
        for (int nt = 0; nt < 8; nt++) {
            int cb = (wn * 8 + nt) * 8;
            int c0 = cb + 2 * q;
            float2 v0 = *reinterpret_cast<float2*>(&zs[row0 * 132 + c0]);
            v0.x = l0 * v0.x + acc[nt][0];
            v0.y = l0 * v0.y + acc[nt][1];
            *reinterpret_cast<float2*>(&zs[row0 * 132 + c0]) = v0;
            float2 v1 = *reinterpret_cast<float2*>(&zs[row1 * 132 + c0]);
            v1.x = l1 * v1.x + acc[nt][2];
            v1.y = l1 * v1.y + acc[nt][3];
            *reinterpret_cast<float2*>(&zs[row1 * 132 + c0]) = v1;
        }
    }
    __syncthreads();

    // --- coalesced float4 store ---
#pragma unroll
    for (int i = 0; i < 8; i++) {
        int idx = tid + i * 256;
        int row = idx >> 5, c4 = (idx & 31) << 2;
        float4 v = *reinterpret_cast<const float4*>(&zs[row * 132 + c4]);
        *reinterpret_cast<float4*>(&out[(size_t)(r0 + row) * ZD + c4]) = v;
    }
}

extern "C" void kernel_launch(void* const* d_in, const int* in_sizes, int n_in,
                              void* d_out, int out_size) {
    const float* pt      = (const float*)d_in[0];
    const float* z       = (const float*)d_in[1];
    const float* dt_norm = (const float*)d_in[2];
    const float* base_U  = (const float*)d_in[3];
    const float* W1      = (const float*)d_in[4];
    const float* b1      = (const float*)d_in[5];
    const float* W2      = (const float*)d_in[6];
    const float* b2      = (const float*)d_in[7];
    const float* W3      = (const float*)d_in[8];
    const float* b3      = (const float*)d_in[9];
    float* out = (float*)d_out;

    cudaFuncSetAttribute(mlp_kernel, cudaFuncAttributeMaxDynamicSharedMemorySize, 222720);
    cudaFuncSetAttribute(dyn_kernel, cudaFuncAttributeMaxDynamicSharedMemorySize, 60160);

    mlp_kernel<<<NBLK, 512, 222720>>>(pt, dt_norm, base_U, W1, b1, W2, b2, W3, b3);
    dyn_kernel<<<NBLK, 256, 60160>>>(z, base_U, out);
}